// round 13
// baseline (speedup 1.0000x reference)
#include <cuda_runtime.h>
#include <cuda_fp16.h>
#include <math.h>
#include <stdint.h>

#define TT   1024
#define HH   2048
#define MI   1408
#define EE   32
#define KTOP 6
#define MSHD 2816
#define NA   (TT * KTOP)

#define N_GATE (EE * HH * MI)     // 92,274,688
#define N_SH   (HH * MSHD)        // 5,767,168
#define N_X    (TT * HH)          // 2,097,152

#define CHE 8                     // experts per convert/gu chunk
#define NCH 4                     // chunks

// ---------------- scratch ---------------------------------------------------
__device__ __align__(16) __half g_gate_h[N_GATE];
__device__ __align__(16) __half g_up_h[N_GATE];
__device__ __align__(16) __half g_down_h[N_GATE];
__device__ __align__(16) __half g_shg_h[N_SH];
__device__ __align__(16) __half g_shu_h[N_SH];
__device__ __align__(16) __half g_shd_h[N_SH];
__device__ __align__(16) __half g_x_h[N_X];
__device__ __align__(16) __half g_act[(size_t)NA * MI];
__device__ __align__(16) __half g_shact[(size_t)TT * MSHD];
__device__ float g_topkw[NA];
__device__ int   g_cnt[EE];
__device__ int   g_list[EE * TT];

// ---------------- helpers ----------------------------------------------------
__device__ __forceinline__ uint32_t s2u(const void* p) {
    uint32_t a;
    asm("{ .reg .u64 t; cvta.to.shared.u64 t, %1; cvt.u32.u64 %0, t; }"
        : "=r"(a) : "l"(p));
    return a;
}
__device__ __forceinline__ uint32_t pk(float lo, float hi) {
    uint32_t r;
    asm("cvt.rn.f16x2.f32 %0, %1, %2;" : "=r"(r) : "f"(hi), "f"(lo));
    return r;
}
__device__ __forceinline__ void mma16(float* c, const uint32_t* a,
                                      uint32_t b0, uint32_t b1)
{
    asm volatile(
      "mma.sync.aligned.m16n8k16.row.col.f32.f16.f16.f32 "
      "{%0,%1,%2,%3}, {%4,%5,%6,%7}, {%8,%9}, {%0,%1,%2,%3};"
      : "+f"(c[0]), "+f"(c[1]), "+f"(c[2]), "+f"(c[3])
      : "r"(a[0]), "r"(a[1]), "r"(a[2]), "r"(a[3]), "r"(b0), "r"(b1));
}
__device__ __forceinline__ void ldsm4(uint32_t* r, uint32_t addr) {
    asm volatile("ldmatrix.sync.aligned.m8n8.x4.shared.b16 {%0,%1,%2,%3}, [%4];"
                 : "=r"(r[0]), "=r"(r[1]), "=r"(r[2]), "=r"(r[3]) : "r"(addr));
}
__device__ __forceinline__ void ldsm4t(uint32_t* r, uint32_t addr) {
    asm volatile("ldmatrix.sync.aligned.m8n8.x4.trans.shared.b16 {%0,%1,%2,%3}, [%4];"
                 : "=r"(r[0]), "=r"(r[1]), "=r"(r[2]), "=r"(r[3]) : "r"(addr));
}
__device__ __forceinline__ void cpa16(uint32_t dst, const void* src) {
    asm volatile("cp.async.cg.shared.global [%0], [%1], 16;"
                 :: "r"(dst), "l"(src) : "memory");
}
__device__ __forceinline__ void cpa16z(uint32_t dst, const void* src, int sz) {
    asm volatile("cp.async.cg.shared.global [%0], [%1], 16, %2;"
                 :: "r"(dst), "l"(src), "r"(sz) : "memory");
}
__device__ __forceinline__ void red2(float* p, float v0, float v1) {
    asm volatile("red.global.add.v2.f32 [%0], {%1, %2};"
                 :: "l"(p), "f"(v0), "f"(v1) : "memory");
}
#define CP_COMMIT asm volatile("cp.async.commit_group;" ::: "memory")
#define CP_WAIT2  asm volatile("cp.async.wait_group 2;"  ::: "memory")

// A tile SMEM: [128 rows][32 halfs] = 64B rows, swizzle: chunk ^= (row>>1)&3
__device__ __forceinline__ uint32_t aoff(int row, int chunk) {
    return (uint32_t)(row * 64 + ((chunk ^ ((row >> 1) & 3)) << 4));
}
// B tile SMEM (row bytes RB = 128 or 256): row = k, swizzle: chunk ^= k&7
__device__ __forceinline__ uint32_t boff(int k, int chunk, int RB) {
    return (uint32_t)(k * RB + (((chunk ^ (k & 7))) << 4));
}

#define STG 16384u   // bytes per pipeline stage

// ---------------- tiny kernels ----------------------------------------------
__global__ void zero_cnt_kernel() {
    if (threadIdx.x < EE) g_cnt[threadIdx.x] = 0;
}

// fp32 -> fp16 streaming convert, 8 elems / thread, L2-streaming hints
__global__ void cvt_kernel(const float4* __restrict__ src,
                           uint4* __restrict__ dst, int n8)
{
    int i = blockIdx.x * blockDim.x + threadIdx.x;
    if (i >= n8) return;
    float4 a = __ldcs(&src[2 * i]);
    float4 b = __ldcs(&src[2 * i + 1]);
    __stcs(&dst[i],
        make_uint4(pk(a.x, a.y), pk(a.z, a.w), pk(b.x, b.y), pk(b.z, b.w)));
}

__global__ void router_kernel(const float* __restrict__ x,
                              const float* __restrict__ wr,
                              const float* __restrict__ bias)
{
    __shared__ float s_sfc[8][32];
    __shared__ float s_sc[8][32];
    int warp = threadIdx.x >> 5, lane = threadIdx.x & 31;
    int t = blockIdx.x * 8 + warp;
    const float* xr = x + (size_t)t * HH;

    float acc = 0.f;
#pragma unroll 8
    for (int h = 0; h < HH; ++h) acc = fmaf(xr[h], wr[h * EE + lane], acc);

    float sc = 1.f / (1.f + expf(-acc));
    s_sc[warp][lane]  = sc;
    s_sfc[warp][lane] = sc + bias[lane];
    __syncwarp();

    if (lane == 0) {
        float gsc[8];
#pragma unroll
        for (int g = 0; g < 8; ++g) {
            const float* v = &s_sfc[warp][g * 4];
            float m1 = -INFINITY; int i1 = 0;
            for (int j = 0; j < 4; ++j) if (v[j] > m1) { m1 = v[j]; i1 = j; }
            float m2 = -INFINITY;
            for (int j = 0; j < 4; ++j) if (j != i1 && v[j] > m2) m2 = v[j];
            gsc[g] = m1 + m2;
        }
        unsigned gsel = 0;
        for (int it = 0; it < 4; ++it) {
            float best = -INFINITY; int bi = 0;
            for (int g = 0; g < 8; ++g)
                if (!((gsel >> g) & 1) && gsc[g] > best) { best = gsc[g]; bi = g; }
            gsel |= 1u << bi;
        }
        float msk[32];
        for (int e = 0; e < 32; ++e)
            msk[e] = ((gsel >> (e >> 2)) & 1) ? s_sfc[warp][e] : -INFINITY;
        for (int k = 0; k < KTOP; ++k) {
            float best = -INFINITY; int bi = 0;
            for (int e = 0; e < 32; ++e)
                if (msk[e] > best) { best = msk[e]; bi = e; }
            msk[bi] = -INFINITY;
            int rowid = t * KTOP + k;
            g_topkw[rowid] = s_sc[warp][bi];
            int pos = atomicAdd(&g_cnt[bi], 1);
            g_list[bi * TT + pos] = rowid;
        }
    }
}

// =============================================================================
// Fused gate+up GEMM (fp16 in, fp16 out): act = silu(A@Bg) * (A@Bu).
// Tile 128M x 64N, BK=32, 8 warps 4m x 2n, cp.async 4-stage pipeline.
// Stage layout: A +0 (8KB), Bg +8192 (4KB), Bu +12288 (4KB).
// =============================================================================
__global__ void __launch_bounds__(256, 2)
gu_hgemm(const __half* __restrict__ A, const __half* __restrict__ Bg_all,
         const __half* __restrict__ Bu_all, __half* __restrict__ C,
         const int* __restrict__ list, const int* __restrict__ cnts,
         int K, int N, int rowDiv, int fixedCnt)
{
    extern __shared__ __align__(16) char sm[];
    int e = blockIdx.z;
    int cnt = cnts ? cnts[e] : fixedCnt;
    int row0 = blockIdx.y * 128;
    if (row0 >= cnt) return;
    int col0 = blockIdx.x * 64;
    const __half* Bg = Bg_all + (size_t)e * K * N + col0;
    const __half* Bu = Bu_all + (size_t)e * K * N + col0;

    uint32_t sb = s2u(sm);
    int tid = threadIdx.x, lane = tid & 31, w = tid >> 5;
    int l4 = lane & 3, g = lane >> 2;
    int wm = (w >> 1) * 32, wn = (w & 1) * 32;

    // ---- cp.async staging maps ----
    int rA = tid >> 2, cA = tid & 3;   // A: rows rA, rA+64; 16B chunk cA
    const __half* pA0; const __half* pA1;
    int szA0 = 0, szA1 = 0;
    {
        int gi = row0 + rA;
        if (gi < cnt) {
            int idx = list ? list[e * TT + gi] : gi;
            pA0 = A + (size_t)(idx / rowDiv) * K + 8 * cA; szA0 = 16;
        } else pA0 = A;
        gi = row0 + rA + 64;
        if (gi < cnt) {
            int idx = list ? list[e * TT + gi] : gi;
            pA1 = A + (size_t)(idx / rowDiv) * K + 8 * cA; szA1 = 16;
        } else pA1 = A;
    }
    uint32_t dA0 = aoff(rA, cA), dA1 = aoff(rA + 64, cA);
    int kB = tid >> 3, cB = tid & 7;
    const __half* pBg = Bg + (size_t)kB * N + 8 * cB;
    const __half* pBu = Bu + (size_t)kB * N + 8 * cB;
    uint32_t dB = 8192 + boff(kB, cB, 128);

#define GU_ISSUE(SO) {                                                        \
        cpa16z(sb + dA0 + (SO), pA0, szA0);                                   \
        cpa16z(sb + dA1 + (SO), pA1, szA1);                                   \
        cpa16(sb + dB + (SO), pBg);                                           \
        cpa16(sb + dB + 4096 + (SO), pBu);                                    \
        pA0 += 32; pA1 += 32;                                                 \
        pBg += (size_t)32 * N; pBu += (size_t)32 * N;                         \
        CP_COMMIT; }

    // ---- ldmatrix lane addresses (stage-relative) ----
    uint32_t adA[2][2], adB[2][2];
    {
        int rl = (lane & 7) + ((lane >> 3) & 1) * 8;
        int kcb = lane >> 4;
#pragma unroll
        for (int mf = 0; mf < 2; ++mf) {
            int row = wm + mf * 16 + rl;
#pragma unroll
            for (int kq = 0; kq < 2; ++kq)
                adA[mf][kq] = sb + aoff(row, kq * 2 + kcb);
        }
#pragma unroll
        for (int nf2 = 0; nf2 < 2; ++nf2) {
            int cb = (wn >> 3) + nf2 * 2 + (lane >> 4);
#pragma unroll
            for (int kq = 0; kq < 2; ++kq) {
                int k = kq * 16 + rl;
                adB[nf2][kq] = sb + 8192 + boff(k, cb, 128);
            }
        }
    }

    float accg[2][4][4], accu[2][4][4];
#pragma unroll
    for (int a = 0; a < 2; ++a)
#pragma unroll
        for (int b = 0; b < 4; ++b)
#pragma unroll
            for (int c = 0; c < 4; ++c) { accg[a][b][c] = 0.f; accu[a][b][c] = 0.f; }

    const int nIter = K / 32;

    GU_ISSUE(0);
    GU_ISSUE(STG);
    GU_ISSUE(2 * STG);

    for (int it = 0; it < nIter; ++it) {
        CP_WAIT2;
        __syncthreads();
        if (it + 3 < nIter) {
            uint32_t so = (uint32_t)((it + 3) & 3) * STG;
            GU_ISSUE(so);
        } else {
            CP_COMMIT;
        }
        uint32_t po = (uint32_t)(it & 3) * STG;

#pragma unroll
        for (int kq = 0; kq < 2; ++kq) {
            uint32_t a0[4], a1[4], b0[4], b1[4];
            ldsm4(a0, adA[0][kq] + po);
            ldsm4(a1, adA[1][kq] + po);
            ldsm4t(b0, adB[0][kq] + po);
            ldsm4t(b1, adB[1][kq] + po);
            mma16(accg[0][0], a0, b0[0], b0[1]);
            mma16(accg[0][1], a0, b0[2], b0[3]);
            mma16(accg[0][2], a0, b1[0], b1[1]);
            mma16(accg[0][3], a0, b1[2], b1[3]);
            mma16(accg[1][0], a1, b0[0], b0[1]);
            mma16(accg[1][1], a1, b0[2], b0[3]);
            mma16(accg[1][2], a1, b1[0], b1[1]);
            mma16(accg[1][3], a1, b1[2], b1[3]);
            ldsm4t(b0, adB[0][kq] + 4096 + po);
            ldsm4t(b1, adB[1][kq] + 4096 + po);
            mma16(accu[0][0], a0, b0[0], b0[1]);
            mma16(accu[0][1], a0, b0[2], b0[3]);
            mma16(accu[0][2], a0, b1[0], b1[1]);
            mma16(accu[0][3], a0, b1[2], b1[3]);
            mma16(accu[1][0], a1, b0[0], b0[1]);
            mma16(accu[1][1], a1, b0[2], b0[3]);
            mma16(accu[1][2], a1, b1[0], b1[1]);
            mma16(accu[1][3], a1, b1[2], b1[3]);
        }
    }

    // epilogue: act = silu(g) * u  (fp16 store)
#pragma unroll
    for (int mf = 0; mf < 2; ++mf)
#pragma unroll
        for (int h = 0; h < 2; ++h) {
            int rl = wm + mf * 16 + g + h * 8;
            int gi = row0 + rl;
            if (gi >= cnt) continue;
            int idx = list ? list[e * TT + gi] : gi;
            __half* Cr = C + (size_t)idx * N + col0;
#pragma unroll
            for (int nf = 0; nf < 4; ++nf) {
                int col = wn + nf * 8 + 2 * l4;
                float g0 = accg[mf][nf][2 * h + 0];
                float g1 = accg[mf][nf][2 * h + 1];
                float u0 = accu[mf][nf][2 * h + 0];
                float u1 = accu[mf][nf][2 * h + 1];
                float s0 = g0 / (1.f + __expf(-g0)) * u0;
                float s1 = g1 / (1.f + __expf(-g1)) * u1;
                *(uint32_t*)(Cr + col) = pk(s0, s1);
            }
        }
#undef GU_ISSUE
}

// =============================================================================
// Down GEMM (fp16 in): tile 128M x 128N, BK=32, 8 warps 2m x 4n, cp.async
// 4-stage. Stage: A +0 (8KB), B +8192 (8KB; 256B rows).
// ATOMIC=0: C[idx] = v (fp32 store).
// ATOMIC=1: out[idx/kdiv] += v * (rowScale ? rowScale[idx] : 1)  (red.v2)
// =============================================================================
template<int ATOMIC>
__global__ void __launch_bounds__(256, 2)
dn_hgemm(const __half* __restrict__ A, const __half* __restrict__ Bb,
         float* __restrict__ C,
         const int* __restrict__ list, const int* __restrict__ cnts,
         const float* __restrict__ rowScale,
         int K, int N, int fixedCnt, int kdiv)
{
    extern __shared__ __align__(16) char sm[];
    int e = blockIdx.z;
    int cnt = cnts ? cnts[e] : fixedCnt;
    int row0 = blockIdx.y * 128;
    if (row0 >= cnt) return;
    int col0 = blockIdx.x * 128;
    const __half* B = Bb + (size_t)e * K * N + col0;

    uint32_t sb = s2u(sm);
    int tid = threadIdx.x, lane = tid & 31, w = tid >> 5;
    int l4 = lane & 3, g = lane >> 2;
    int wm = (w & 1) * 64, wn = (w >> 1) * 32;

    int rA = tid >> 2, cA = tid & 3;
    const __half* pA0; const __half* pA1;
    int szA0 = 0, szA1 = 0;
    {
        int gi = row0 + rA;
        if (gi < cnt) {
            int idx = list ? list[e * TT + gi] : gi;
            pA0 = A + (size_t)idx * K + 8 * cA; szA0 = 16;
        } else pA0 = A;
        gi = row0 + rA + 64;
        if (gi < cnt) {
            int idx = list ? list[e * TT + gi] : gi;
            pA1 = A + (size_t)idx * K + 8 * cA; szA1 = 16;
        } else pA1 = A;
    }
    uint32_t dA0 = aoff(rA, cA), dA1 = aoff(rA + 64, cA);
    int kB = tid >> 4, cB = tid & 15;
    const __half* pB0 = B + (size_t)kB * N + 8 * cB;
    const __half* pB1 = B + (size_t)(kB + 16) * N + 8 * cB;
    uint32_t dB0 = 8192 + boff(kB, cB, 256);
    uint32_t dB1 = 8192 + boff(kB + 16, cB, 256);

#define DN_ISSUE(SO) {                                                        \
        cpa16z(sb + dA0 + (SO), pA0, szA0);                                   \
        cpa16z(sb + dA1 + (SO), pA1, szA1);                                   \
        cpa16(sb + dB0 + (SO), pB0);                                          \
        cpa16(sb + dB1 + (SO), pB1);                                          \
        pA0 += 32; pA1 += 32;                                                 \
        pB0 += (size_t)32 * N; pB1 += (size_t)32 * N;                         \
        CP_COMMIT; }

    uint32_t adA[4][2], adB[2][2];
    {
        int rl = (lane & 7) + ((lane >> 3) & 1) * 8;
        int kcb = lane >> 4;
#pragma unroll
        for (int mf = 0; mf < 4; ++mf) {
            int row = wm + mf * 16 + rl;
#pragma unroll
            for (int kq = 0; kq < 2; ++kq)
                adA[mf][kq] = sb + aoff(row, kq * 2 + kcb);
        }
#pragma unroll
        for (int nf2 = 0; nf2 < 2; ++nf2) {
            int cb = (wn >> 3) + nf2 * 2 + (lane >> 4);
#pragma unroll
            for (int kq = 0; kq < 2; ++kq) {
                int k = kq * 16 + rl;
                adB[nf2][kq] = sb + 8192 + boff(k, cb, 256);
            }
        }
    }

    float acc[4][4][4];
#pragma unroll
    for (int a = 0; a < 4; ++a)
#pragma unroll
        for (int b = 0; b < 4; ++b)
#pragma unroll
            for (int c = 0; c < 4; ++c) acc[a][b][c] = 0.f;

    const int nIter = K / 32;

    DN_ISSUE(0);
    DN_ISSUE(STG);
    DN_ISSUE(2 * STG);

    for (int it = 0; it < nIter; ++it) {
        CP_WAIT2;
        __syncthreads();
        if (it + 3 < nIter) {
            uint32_t so = (uint32_t)((it + 3) & 3) * STG;
            DN_ISSUE(so);
        } else {
            CP_COMMIT;
        }
        uint32_t po = (uint32_t)(it & 3) * STG;

#pragma unroll
        for (int kq = 0; kq < 2; ++kq) {
            uint32_t b0[4], b1[4];
            ldsm4t(b0, adB[0][kq] + po);
            ldsm4t(b1, adB[1][kq] + po);
#pragma unroll
            for (int mf = 0; mf < 4; ++mf) {
                uint32_t a[4];
                ldsm4(a, adA[mf][kq] + po);
                mma16(acc[mf][0], a, b0[0], b0[1]);
                mma16(acc[mf][1], a, b0[2], b0[3]);
                mma16(acc[mf][2], a, b1[0], b1[1]);
                mma16(acc[mf][3], a, b1[2], b1[3]);
            }
        }
    }

    // epilogue
#pragma unroll
    for (int mf = 0; mf < 4; ++mf)
#pragma unroll
        for (int h = 0; h < 2; ++h) {
            int rl = wm + mf * 16 + g + h * 8;
            int gi = row0 + rl;
            if (gi >= cnt) continue;
            int idx = list ? list[e * TT + gi] : gi;
            float s = 1.f;
            float* Cr;
            if (ATOMIC) {
                if (rowScale) s = rowScale[idx];
                Cr = C + (size_t)(idx / kdiv) * N + col0;
            } else {
                Cr = C + (size_t)idx * N + col0;
            }
#pragma unroll
            for (int nf = 0; nf < 4; ++nf) {
                int col = wn + nf * 8 + 2 * l4;
                float v0 = acc[mf][nf][2 * h + 0];
                float v1 = acc[mf][nf][2 * h + 1];
                if (ATOMIC) {
                    red2(Cr + col, v0 * s, v1 * s);
                } else {
                    *(float2*)(Cr + col) = make_float2(v0, v1);
                }
            }
        }
#undef DN_ISSUE
}

// ---------------- launch ------------------------------------------------------
extern "C" void kernel_launch(void* const* d_in, const int* in_sizes, int n_in,
                              void* d_out, int out_size)
{
    const float* x      = (const float*)d_in[0];
    const float* wr     = (const float*)d_in[1];
    const float* bias   = (const float*)d_in[2];
    const float* gate_w = (const float*)d_in[3];
    const float* up_w   = (const float*)d_in[4];
    const float* down_w = (const float*)d_in[5];
    const float* shg    = (const float*)d_in[6];
    const float* shu    = (const float*)d_in[7];
    const float* shd    = (const float*)d_in[8];
    float* out = (float*)d_out;

    void *p_act, *p_shact, *p_w, *p_cnt, *p_list;
    void *p_gh, *p_uh, *p_dh, *p_sg, *p_su, *p_sd, *p_xh;
    cudaGetSymbolAddress(&p_act,   g_act);
    cudaGetSymbolAddress(&p_shact, g_shact);
    cudaGetSymbolAddress(&p_w,     g_topkw);
    cudaGetSymbolAddress(&p_cnt,   g_cnt);
    cudaGetSymbolAddress(&p_list,  g_list);
    cudaGetSymbolAddress(&p_gh, g_gate_h);
    cudaGetSymbolAddress(&p_uh, g_up_h);
    cudaGetSymbolAddress(&p_dh, g_down_h);
    cudaGetSymbolAddress(&p_sg, g_shg_h);
    cudaGetSymbolAddress(&p_su, g_shu_h);
    cudaGetSymbolAddress(&p_sd, g_shd_h);
    cudaGetSymbolAddress(&p_xh, g_x_h);

    const int SMEM = 4 * (int)STG;   // 65536
    cudaFuncSetAttribute(gu_hgemm,    cudaFuncAttributeMaxDynamicSharedMemorySize, SMEM);
    cudaFuncSetAttribute(dn_hgemm<0>, cudaFuncAttributeMaxDynamicSharedMemorySize, SMEM);
    cudaFuncSetAttribute(dn_hgemm<1>, cudaFuncAttributeMaxDynamicSharedMemorySize, SMEM);

    // ONE extra stream only (more streams trip the device-memory guard).
    cudaStream_t s1;
    cudaStreamCreateWithFlags(&s1, cudaStreamNonBlocking);
    cudaEvent_t evFork, evX, evRt, evJoin, evCvt[NCH];
    cudaEventCreateWithFlags(&evFork, cudaEventDisableTiming);
    cudaEventCreateWithFlags(&evX,    cudaEventDisableTiming);
    cudaEventCreateWithFlags(&evRt,   cudaEventDisableTiming);
    cudaEventCreateWithFlags(&evJoin, cudaEventDisableTiming);
    for (int c = 0; c < NCH; ++c)
        cudaEventCreateWithFlags(&evCvt[c], cudaEventDisableTiming);

    cudaEventRecord(evFork, 0);
    cudaStreamWaitEvent(s1, evFork, 0);

    // ---- s1: zero out, router, shared converts, chunked gate/up converts ----
    cudaMemsetAsync(out, 0, (size_t)TT * HH * sizeof(float), s1);
    zero_cnt_kernel<<<1, 32, 0, s1>>>();
    router_kernel<<<TT / 8, 256, 0, s1>>>(x, wr, bias);
    cudaEventRecord(evRt, s1);
    cvt_kernel<<<(N_SH / 8 + 255) / 256, 256, 0, s1>>>(
        (const float4*)shg, (uint4*)p_sg, N_SH / 8);
    cvt_kernel<<<(N_SH / 8 + 255) / 256, 256, 0, s1>>>(
        (const float4*)shu, (uint4*)p_su, N_SH / 8);
    cvt_kernel<<<(N_SH / 8 + 255) / 256, 256, 0, s1>>>(
        (const float4*)shd, (uint4*)p_sd, N_SH / 8);
    const size_t chW = (size_t)CHE * HH * MI;       // elems per chunk
    const int chN8 = (int)(chW / 8);
    for (int c = 0; c < NCH; ++c) {
        cvt_kernel<<<(chN8 + 255) / 256, 256, 0, s1>>>(
            (const float4*)(gate_w + c * chW),
            (uint4*)((__half*)p_gh + c * chW), chN8);
        cvt_kernel<<<(chN8 + 255) / 256, 256, 0, s1>>>(
            (const float4*)(up_w + c * chW),
            (uint4*)((__half*)p_uh + c * chW), chN8);
        cudaEventRecord(evCvt[c], s1);
    }

    // ---- s0: cvt_x, then cvt_down while waiting on chunk-0 convert ----
    cvt_kernel<<<(N_X / 8 + 255) / 256, 256>>>(
        (const float4*)x, (uint4*)p_xh, N_X / 8);
    cudaEventRecord(evX, 0);
    cvt_kernel<<<(N_GATE / 8 + 255) / 256, 256>>>(
        (const float4*)down_w, (uint4*)p_dh, N_GATE / 8);

    // ---- s1 (after converts): shared chain (atomic into zeroed out) ----
    cudaStreamWaitEvent(s1, evX, 0);
    gu_hgemm<<<dim3(MSHD / 64, TT / 128, 1), 256, SMEM, s1>>>(
        (const __half*)p_xh, (const __half*)p_sg, (const __half*)p_su,
        (__half*)p_shact, nullptr, nullptr, HH, MSHD, 1, TT);
    dn_hgemm<1><<<dim3(HH / 128, TT / 128, 1), 256, SMEM, s1>>>(
        (const __half*)p_shact, (const __half*)p_sd, out,
        nullptr, nullptr, nullptr, MSHD, HH, TT, 1);
    cudaEventRecord(evJoin, s1);

    // ---- s0: gu chunks (each gated on its convert), then routed down ----
    cudaStreamWaitEvent(0, evRt, 0);
    for (int c = 0; c < NCH; ++c) {
        cudaStreamWaitEvent(0, evCvt[c], 0);
        gu_hgemm<<<dim3(MI / 64, TT / 128, CHE), 256, SMEM>>>(
            (const __half*)p_xh,
            (const __half*)p_gh + c * chW,
            (const __half*)p_uh + c * chW,
            (__half*)p_act,
            (const int*)p_list + c * CHE * TT,
            (const int*)p_cnt + c * CHE,
            HH, MI, KTOP, 0);
    }
    // dn_routed needs only gu chunks (s0 order) + cvt_down (s0 order) + memset
    // (s1, transitively ordered before evCvt events we already waited on).
    dn_hgemm<1><<<dim3(HH / 128, TT / 128, EE), 256, SMEM>>>(
        (const __half*)p_act, (const __half*)p_dh, out,
        (const int*)p_list, (const int*)p_cnt, (const float*)p_w,
        MI, HH, 0, KTOP);

    // ordering join so all s1 work is captured before stream 0 completes
    cudaStreamWaitEvent(0, evJoin, 0);
}

// round 14
// speedup vs baseline: 1.0539x; 1.0539x over previous
#include <cuda_runtime.h>
#include <cuda_fp16.h>
#include <math.h>
#include <stdint.h>

#define TT   1024
#define HH   2048
#define MI   1408
#define EE   32
#define KTOP 6
#define MSHD 2816
#define NA   (TT * KTOP)
#define N_X  (TT * HH)

// ---------------- scratch ---------------------------------------------------
__device__ __align__(16) __half g_x_h[N_X];
__device__ __align__(16) __half g_act[(size_t)NA * MI];
__device__ __align__(16) __half g_shact[(size_t)TT * MSHD];
__device__ float g_topkw[NA];
__device__ int   g_cnt[EE];
__device__ int   g_list[EE * TT];

// ---------------- helpers ----------------------------------------------------
__device__ __forceinline__ uint32_t s2u(const void* p) {
    uint32_t a;
    asm("{ .reg .u64 t; cvta.to.shared.u64 t, %1; cvt.u32.u64 %0, t; }"
        : "=r"(a) : "l"(p));
    return a;
}
__device__ __forceinline__ uint32_t pk(float lo, float hi) {
    uint32_t r;
    asm("cvt.rn.f16x2.f32 %0, %1, %2;" : "=r"(r) : "f"(hi), "f"(lo));
    return r;
}
__device__ __forceinline__ uint4 pk4(float4 a, float4 b) {
    return make_uint4(pk(a.x, a.y), pk(a.z, a.w), pk(b.x, b.y), pk(b.z, b.w));
}
__device__ __forceinline__ void mma16(float* c, const uint32_t* a,
                                      uint32_t b0, uint32_t b1)
{
    asm volatile(
      "mma.sync.aligned.m16n8k16.row.col.f32.f16.f16.f32 "
      "{%0,%1,%2,%3}, {%4,%5,%6,%7}, {%8,%9}, {%0,%1,%2,%3};"
      : "+f"(c[0]), "+f"(c[1]), "+f"(c[2]), "+f"(c[3])
      : "r"(a[0]), "r"(a[1]), "r"(a[2]), "r"(a[3]), "r"(b0), "r"(b1));
}
__device__ __forceinline__ void ldsm4(uint32_t* r, uint32_t addr) {
    asm volatile("ldmatrix.sync.aligned.m8n8.x4.shared.b16 {%0,%1,%2,%3}, [%4];"
                 : "=r"(r[0]), "=r"(r[1]), "=r"(r[2]), "=r"(r[3]) : "r"(addr));
}
__device__ __forceinline__ void ldsm4t(uint32_t* r, uint32_t addr) {
    asm volatile("ldmatrix.sync.aligned.m8n8.x4.trans.shared.b16 {%0,%1,%2,%3}, [%4];"
                 : "=r"(r[0]), "=r"(r[1]), "=r"(r[2]), "=r"(r[3]) : "r"(addr));
}
__device__ __forceinline__ void cpa16(uint32_t dst, const void* src) {
    asm volatile("cp.async.cg.shared.global [%0], [%1], 16;"
                 :: "r"(dst), "l"(src) : "memory");
}
__device__ __forceinline__ void cpa16z(uint32_t dst, const void* src, int sz) {
    asm volatile("cp.async.cg.shared.global [%0], [%1], 16, %2;"
                 :: "r"(dst), "l"(src), "r"(sz) : "memory");
}
__device__ __forceinline__ void red2(float* p, float v0, float v1) {
    asm volatile("red.global.add.v2.f32 [%0], {%1, %2};"
                 :: "l"(p), "f"(v0), "f"(v1) : "memory");
}
#define CP_COMMIT asm volatile("cp.async.commit_group;" ::: "memory")
#define CP_WAIT1  asm volatile("cp.async.wait_group 1;"  ::: "memory")

// A tile SMEM: [128 rows][32 halfs] = 64B rows, swizzle: chunk ^= (row>>1)&3
__device__ __forceinline__ uint32_t aoff(int row, int chunk) {
    return (uint32_t)(row * 64 + ((chunk ^ ((row >> 1) & 3)) << 4));
}
// B fp16 tile (row bytes RB = 128 or 256): row = k, swizzle: chunk ^= k&7
__device__ __forceinline__ uint32_t boff(int k, int chunk, int RB) {
    return (uint32_t)(k * RB + (((chunk ^ (k & 7))) << 4));
}

// SMEM maps (both GEMMs, 3-stage): A fp16 stages [0,24576),
// B fp32 stages [24576, 73728) (16KB each), B fp16 single buffer [73728, 81920)
#define OFF_B32 24576u
#define OFF_B16 73728u
#define SMEM_SZ 81920

// ---------------- tiny kernels ----------------------------------------------
__global__ void zero_cnt_kernel() {
    if (threadIdx.x < EE) g_cnt[threadIdx.x] = 0;
}

__global__ void cvt_kernel(const float4* __restrict__ src,
                           uint4* __restrict__ dst, int n8)
{
    int i = blockIdx.x * blockDim.x + threadIdx.x;
    if (i >= n8) return;
    float4 a = __ldcs(&src[2 * i]);
    float4 b = __ldcs(&src[2 * i + 1]);
    __stcs(&dst[i], pk4(a, b));
}

__global__ void router_kernel(const float* __restrict__ x,
                              const float* __restrict__ wr,
                              const float* __restrict__ bias)
{
    __shared__ float s_sfc[8][32];
    __shared__ float s_sc[8][32];
    int warp = threadIdx.x >> 5, lane = threadIdx.x & 31;
    int t = blockIdx.x * 8 + warp;
    const float* xr = x + (size_t)t * HH;

    float acc = 0.f;
#pragma unroll 8
    for (int h = 0; h < HH; ++h) acc = fmaf(xr[h], wr[h * EE + lane], acc);

    float sc = 1.f / (1.f + expf(-acc));
    s_sc[warp][lane]  = sc;
    s_sfc[warp][lane] = sc + bias[lane];
    __syncwarp();

    if (lane == 0) {
        float gsc[8];
#pragma unroll
        for (int g = 0; g < 8; ++g) {
            const float* v = &s_sfc[warp][g * 4];
            float m1 = -INFINITY; int i1 = 0;
            for (int j = 0; j < 4; ++j) if (v[j] > m1) { m1 = v[j]; i1 = j; }
            float m2 = -INFINITY;
            for (int j = 0; j < 4; ++j) if (j != i1 && v[j] > m2) m2 = v[j];
            gsc[g] = m1 + m2;
        }
        unsigned gsel = 0;
        for (int it = 0; it < 4; ++it) {
            float best = -INFINITY; int bi = 0;
            for (int g = 0; g < 8; ++g)
                if (!((gsel >> g) & 1) && gsc[g] > best) { best = gsc[g]; bi = g; }
            gsel |= 1u << bi;
        }
        float msk[32];
        for (int e = 0; e < 32; ++e)
            msk[e] = ((gsel >> (e >> 2)) & 1) ? s_sfc[warp][e] : -INFINITY;
        for (int k = 0; k < KTOP; ++k) {
            float best = -INFINITY; int bi = 0;
            for (int e = 0; e < 32; ++e)
                if (msk[e] > best) { best = msk[e]; bi = e; }
            msk[bi] = -INFINITY;
            int rowid = t * KTOP + k;
            g_topkw[rowid] = s_sc[warp][bi];
            int pos = atomicAdd(&g_cnt[bi], 1);
            g_list[bi * TT + pos] = rowid;
        }
    }
}

// =============================================================================
// Fused gate+up GEMM, fp32 weights staged directly.
// Tile 128M x 64N, BK=32, 8 warps 4m x 2n. 3-stage cp.async on A(fp16 from
// g_x_h) + Bg/Bu(fp32). Per-iter SMEM cvt fp32->fp16 into the ldmatrix layout.
// =============================================================================
__global__ void __launch_bounds__(256, 2)
gu_hgemm(const __half* __restrict__ A, const float* __restrict__ Bg_all,
         const float* __restrict__ Bu_all, __half* __restrict__ C,
         const int* __restrict__ list, const int* __restrict__ cnts,
         int K, int N, int rowDiv, int fixedCnt)
{
    extern __shared__ __align__(16) char sm[];
    int e = blockIdx.z;
    int cnt = cnts ? cnts[e] : fixedCnt;
    int row0 = blockIdx.y * 128;
    if (row0 >= cnt) return;
    int col0 = blockIdx.x * 64;
    const float* Bg = Bg_all + (size_t)e * K * N + col0;
    const float* Bu = Bu_all + (size_t)e * K * N + col0;

    uint32_t sb = s2u(sm);
    int tid = threadIdx.x, lane = tid & 31, w = tid >> 5;
    int l4 = lane & 3, g = lane >> 2;
    int wm = (w >> 1) * 32, wn = (w & 1) * 32;

    // ---- A cp.async map (fp16) ----
    int rA = tid >> 2, cA = tid & 3;
    const __half* pA0; const __half* pA1;
    int szA0 = 0, szA1 = 0;
    {
        int gi = row0 + rA;
        if (gi < cnt) {
            int idx = list ? list[e * TT + gi] : gi;
            pA0 = A + (size_t)(idx / rowDiv) * K + 8 * cA; szA0 = 16;
        } else pA0 = A;
        gi = row0 + rA + 64;
        if (gi < cnt) {
            int idx = list ? list[e * TT + gi] : gi;
            pA1 = A + (size_t)(idx / rowDiv) * K + 8 * cA; szA1 = 16;
        } else pA1 = A;
    }
    uint32_t dA0 = aoff(rA, cA), dA1 = aoff(rA + 64, cA);

    // ---- B fp32 cp.async map: 32 k-rows x 64 floats (256B rows) per matrix
    int kS = tid >> 3, cS = tid & 7;           // chunks cS and cS+8 (16B each)
    const float* pBg0 = Bg + (size_t)kS * N + 4 * cS;
    const float* pBg1 = Bg + (size_t)kS * N + 4 * (cS + 8);
    const float* pBu0 = Bu + (size_t)kS * N + 4 * cS;
    const float* pBu1 = Bu + (size_t)kS * N + 4 * (cS + 8);
    uint32_t dB0 = (uint32_t)(kS * 256 + cS * 16);
    uint32_t dB1 = (uint32_t)(kS * 256 + (cS + 8) * 16);

#define GU_ISSUE(S) {                                                         \
        uint32_t soA = (uint32_t)(S) * 8192u;                                 \
        uint32_t soB = OFF_B32 + (uint32_t)(S) * 16384u;                      \
        cpa16z(sb + soA + dA0, pA0, szA0);                                    \
        cpa16z(sb + soA + dA1, pA1, szA1);                                    \
        cpa16(sb + soB + dB0, pBg0);                                          \
        cpa16(sb + soB + dB1, pBg1);                                          \
        cpa16(sb + soB + 8192 + dB0, pBu0);                                   \
        cpa16(sb + soB + 8192 + dB1, pBu1);                                   \
        pA0 += 32; pA1 += 32;                                                 \
        pBg0 += (size_t)32 * N; pBg1 += (size_t)32 * N;                       \
        pBu0 += (size_t)32 * N; pBu1 += (size_t)32 * N;                       \
        CP_COMMIT; }

    // ---- ldmatrix lane addresses ----
    uint32_t adA[2][2], adB[2][2];
    {
        int rl = (lane & 7) + ((lane >> 3) & 1) * 8;
        int kcb = lane >> 4;
#pragma unroll
        for (int mf = 0; mf < 2; ++mf) {
            int row = wm + mf * 16 + rl;
#pragma unroll
            for (int kq = 0; kq < 2; ++kq)
                adA[mf][kq] = sb + aoff(row, kq * 2 + kcb);
        }
#pragma unroll
        for (int nf2 = 0; nf2 < 2; ++nf2) {
            int cb = (wn >> 3) + nf2 * 2 + (lane >> 4);
#pragma unroll
            for (int kq = 0; kq < 2; ++kq) {
                int k = kq * 16 + rl;
                adB[nf2][kq] = sb + OFF_B16 + boff(k, cb, 128);
            }
        }
    }

    float accg[2][4][4], accu[2][4][4];
#pragma unroll
    for (int a = 0; a < 2; ++a)
#pragma unroll
        for (int b = 0; b < 4; ++b)
#pragma unroll
            for (int c = 0; c < 4; ++c) { accg[a][b][c] = 0.f; accu[a][b][c] = 0.f; }

    const int nIter = K / 32;
    GU_ISSUE(0);
    GU_ISSUE(1);

    int ps = 0, is = 2;
    int kk = tid >> 3, cc = tid & 7;
    for (int it = 0; it < nIter; ++it) {
        CP_WAIT1;
        __syncthreads();
        if (it + 2 < nIter) { GU_ISSUE(is); } else { CP_COMMIT; }

        // ---- cvt fp32 stage ps -> fp16 buffer ----
        {
            uint32_t b32 = OFF_B32 + (uint32_t)ps * 16384u
                         + (uint32_t)(kk * 256 + cc * 32);
            const float4* sg = (const float4*)(sm + b32);
            float4 a0 = sg[0], a1 = sg[1];
            *(uint4*)(sm + OFF_B16 + boff(kk, cc, 128)) = pk4(a0, a1);
            const float4* su = (const float4*)(sm + b32 + 8192);
            float4 b0v = su[0], b1v = su[1];
            *(uint4*)(sm + OFF_B16 + 4096 + boff(kk, cc, 128)) = pk4(b0v, b1v);
        }
        __syncthreads();

        uint32_t poA = (uint32_t)ps * 8192u;
#pragma unroll
        for (int kq = 0; kq < 2; ++kq) {
            uint32_t a0[4], a1[4], b0[4], b1[4];
            ldsm4(a0, adA[0][kq] + poA);
            ldsm4(a1, adA[1][kq] + poA);
            ldsm4t(b0, adB[0][kq]);
            ldsm4t(b1, adB[1][kq]);
            mma16(accg[0][0], a0, b0[0], b0[1]);
            mma16(accg[0][1], a0, b0[2], b0[3]);
            mma16(accg[0][2], a0, b1[0], b1[1]);
            mma16(accg[0][3], a0, b1[2], b1[3]);
            mma16(accg[1][0], a1, b0[0], b0[1]);
            mma16(accg[1][1], a1, b0[2], b0[3]);
            mma16(accg[1][2], a1, b1[0], b1[1]);
            mma16(accg[1][3], a1, b1[2], b1[3]);
            ldsm4t(b0, adB[0][kq] + 4096);
            ldsm4t(b1, adB[1][kq] + 4096);
            mma16(accu[0][0], a0, b0[0], b0[1]);
            mma16(accu[0][1], a0, b0[2], b0[3]);
            mma16(accu[0][2], a0, b1[0], b1[1]);
            mma16(accu[0][3], a0, b1[2], b1[3]);
            mma16(accu[1][0], a1, b0[0], b0[1]);
            mma16(accu[1][1], a1, b0[2], b0[3]);
            mma16(accu[1][2], a1, b1[0], b1[1]);
            mma16(accu[1][3], a1, b1[2], b1[3]);
        }
        ps = (ps == 2) ? 0 : ps + 1;
        is = (is == 2) ? 0 : is + 1;
    }

    // epilogue: act = silu(g) * u  (fp16 store)
#pragma unroll
    for (int mf = 0; mf < 2; ++mf)
#pragma unroll
        for (int h = 0; h < 2; ++h) {
            int rl = wm + mf * 16 + g + h * 8;
            int gi = row0 + rl;
            if (gi >= cnt) continue;
            int idx = list ? list[e * TT + gi] : gi;
            __half* Cr = C + (size_t)idx * N + col0;
#pragma unroll
            for (int nf = 0; nf < 4; ++nf) {
                int col = wn + nf * 8 + 2 * l4;
                float g0 = accg[mf][nf][2 * h + 0];
                float g1 = accg[mf][nf][2 * h + 1];
                float u0 = accu[mf][nf][2 * h + 0];
                float u1 = accu[mf][nf][2 * h + 1];
                float s0 = g0 / (1.f + __expf(-g0)) * u0;
                float s1 = g1 / (1.f + __expf(-g1)) * u1;
                *(uint32_t*)(Cr + col) = pk(s0, s1);
            }
        }
#undef GU_ISSUE
}

// =============================================================================
// Down GEMM, fp32 weights staged directly. Tile 128M x 128N, BK=32,
// 8 warps 2m x 4n, 3-stage cp.async + per-iter SMEM cvt.
// ATOMIC=0: C[idx] = v. ATOMIC=1: out[idx/kdiv] += v * scale (red.v2).
// =============================================================================
template<int ATOMIC>
__global__ void __launch_bounds__(256, 2)
dn_hgemm(const __half* __restrict__ A, const float* __restrict__ Bb,
         float* __restrict__ C,
         const int* __restrict__ list, const int* __restrict__ cnts,
         const float* __restrict__ rowScale,
         int K, int N, int fixedCnt, int kdiv)
{
    extern __shared__ __align__(16) char sm[];
    int e = blockIdx.z;
    int cnt = cnts ? cnts[e] : fixedCnt;
    int row0 = blockIdx.y * 128;
    if (row0 >= cnt) return;
    int col0 = blockIdx.x * 128;
    const float* B = Bb + (size_t)e * K * N + col0;

    uint32_t sb = s2u(sm);
    int tid = threadIdx.x, lane = tid & 31, w = tid >> 5;
    int l4 = lane & 3, g = lane >> 2;
    int wm = (w & 1) * 64, wn = (w >> 1) * 32;

    int rA = tid >> 2, cA = tid & 3;
    const __half* pA0; const __half* pA1;
    int szA0 = 0, szA1 = 0;
    {
        int gi = row0 + rA;
        if (gi < cnt) {
            int idx = list ? list[e * TT + gi] : gi;
            pA0 = A + (size_t)idx * K + 8 * cA; szA0 = 16;
        } else pA0 = A;
        gi = row0 + rA + 64;
        if (gi < cnt) {
            int idx = list ? list[e * TT + gi] : gi;
            pA1 = A + (size_t)idx * K + 8 * cA; szA1 = 16;
        } else pA1 = A;
    }
    uint32_t dA0 = aoff(rA, cA), dA1 = aoff(rA + 64, cA);

    // B fp32: 32 k-rows x 128 floats (512B rows); 4 chunks / thread
    int kS = tid >> 3, cS = tid & 7;
    const float* pB0 = B + (size_t)kS * N + 4 * cS;
    const float* pB1 = B + (size_t)kS * N + 4 * (cS + 8);
    const float* pB2 = B + (size_t)kS * N + 4 * (cS + 16);
    const float* pB3 = B + (size_t)kS * N + 4 * (cS + 24);
    uint32_t dB0 = (uint32_t)(kS * 512 + cS * 16);
    uint32_t dB1 = dB0 + 128, dB2 = dB0 + 256, dB3 = dB0 + 384;

#define DN_ISSUE(S) {                                                         \
        uint32_t soA = (uint32_t)(S) * 8192u;                                 \
        uint32_t soB = OFF_B32 + (uint32_t)(S) * 16384u;                      \
        cpa16z(sb + soA + dA0, pA0, szA0);                                    \
        cpa16z(sb + soA + dA1, pA1, szA1);                                    \
        cpa16(sb + soB + dB0, pB0);                                           \
        cpa16(sb + soB + dB1, pB1);                                           \
        cpa16(sb + soB + dB2, pB2);                                           \
        cpa16(sb + soB + dB3, pB3);                                           \
        pA0 += 32; pA1 += 32;                                                 \
        pB0 += (size_t)32 * N; pB1 += (size_t)32 * N;                         \
        pB2 += (size_t)32 * N; pB3 += (size_t)32 * N;                         \
        CP_COMMIT; }

    uint32_t adA[4][2], adB[2][2];
    {
        int rl = (lane & 7) + ((lane >> 3) & 1) * 8;
        int kcb = lane >> 4;
#pragma unroll
        for (int mf = 0; mf < 4; ++mf) {
            int row = wm + mf * 16 + rl;
#pragma unroll
            for (int kq = 0; kq < 2; ++kq)
                adA[mf][kq] = sb + aoff(row, kq * 2 + kcb);
        }
#pragma unroll
        for (int nf2 = 0; nf2 < 2; ++nf2) {
            int cb = (wn >> 3) + nf2 * 2 + (lane >> 4);
#pragma unroll
            for (int kq = 0; kq < 2; ++kq) {
                int k = kq * 16 + rl;
                adB[nf2][kq] = sb + OFF_B16 + boff(k, cb, 256);
            }
        }
    }

    float acc[4][4][4];
#pragma unroll
    for (int a = 0; a < 4; ++a)
#pragma unroll
        for (int b = 0; b < 4; ++b)
#pragma unroll
            for (int c = 0; c < 4; ++c) acc[a][b][c] = 0.f;

    const int nIter = K / 32;
    DN_ISSUE(0);
    DN_ISSUE(1);

    int ps = 0, is = 2;
    int kk = tid >> 3, cc = tid & 7;
    for (int it = 0; it < nIter; ++it) {
        CP_WAIT1;
        __syncthreads();
        if (it + 2 < nIter) { DN_ISSUE(is); } else { CP_COMMIT; }

        // cvt fp32 stage ps -> fp16 buffer (2 chunks / thread)
        {
            uint32_t b32 = OFF_B32 + (uint32_t)ps * 16384u + (uint32_t)(kk * 512);
            const float4* s0 = (const float4*)(sm + b32 + cc * 32);
            float4 a0 = s0[0], a1 = s0[1];
            *(uint4*)(sm + OFF_B16 + boff(kk, cc, 256)) = pk4(a0, a1);
            const float4* s1 = (const float4*)(sm + b32 + (cc + 8) * 32);
            float4 b0v = s1[0], b1v = s1[1];
            *(uint4*)(sm + OFF_B16 + boff(kk, cc + 8, 256)) = pk4(b0v, b1v);
        }
        __syncthreads();

        uint32_t poA = (uint32_t)ps * 8192u;
#pragma unroll
        for (int kq = 0; kq < 2; ++kq) {
            uint32_t b0[4], b1[4];
            ldsm4t(b0, adB[0][kq]);
            ldsm4t(b1, adB[1][kq]);
#pragma unroll
            for (int mf = 0; mf < 4; ++mf) {
                uint32_t a[4];
                ldsm4(a, adA[mf][kq] + poA);
                mma16(acc[mf][0], a, b0[0], b0[1]);
                mma16(acc[mf][1], a, b0[2], b0[3]);
                mma16(acc[mf][2], a, b1[0], b1[1]);
                mma16(acc[mf][3], a, b1[2], b1[3]);
            }
        }
        ps = (ps == 2) ? 0 : ps + 1;
        is = (is == 2) ? 0 : is + 1;
    }

    // epilogue
#pragma unroll
    for (int mf = 0; mf < 4; ++mf)
#pragma unroll
        for (int h = 0; h < 2; ++h) {
            int rl = wm + mf * 16 + g + h * 8;
            int gi = row0 + rl;
            if (gi >= cnt) continue;
            int idx = list ? list[e * TT + gi] : gi;
            float s = 1.f;
            float* Cr;
            if (ATOMIC) {
                if (rowScale) s = rowScale[idx];
                Cr = C + (size_t)(idx / kdiv) * N + col0;
            } else {
                Cr = C + (size_t)idx * N + col0;
            }
#pragma unroll
            for (int nf = 0; nf < 4; ++nf) {
                int col = wn + nf * 8 + 2 * l4;
                float v0 = acc[mf][nf][2 * h + 0];
                float v1 = acc[mf][nf][2 * h + 1];
                if (ATOMIC) {
                    red2(Cr + col, v0 * s, v1 * s);
                } else {
                    *(float2*)(Cr + col) = make_float2(v0, v1);
                }
            }
        }
#undef DN_ISSUE
}

// ---------------- launch ------------------------------------------------------
extern "C" void kernel_launch(void* const* d_in, const int* in_sizes, int n_in,
                              void* d_out, int out_size)
{
    const float* x      = (const float*)d_in[0];
    const float* wr     = (const float*)d_in[1];
    const float* bias   = (const float*)d_in[2];
    const float* gate_w = (const float*)d_in[3];
    const float* up_w   = (const float*)d_in[4];
    const float* down_w = (const float*)d_in[5];
    const float* shg    = (const float*)d_in[6];
    const float* shu    = (const float*)d_in[7];
    const float* shd    = (const float*)d_in[8];
    float* out = (float*)d_out;

    void *p_act, *p_shact, *p_w, *p_cnt, *p_list, *p_xh;
    cudaGetSymbolAddress(&p_act,   g_act);
    cudaGetSymbolAddress(&p_shact, g_shact);
    cudaGetSymbolAddress(&p_w,     g_topkw);
    cudaGetSymbolAddress(&p_cnt,   g_cnt);
    cudaGetSymbolAddress(&p_list,  g_list);
    cudaGetSymbolAddress(&p_xh,    g_x_h);

    cudaFuncSetAttribute(gu_hgemm,    cudaFuncAttributeMaxDynamicSharedMemorySize, SMEM_SZ);
    cudaFuncSetAttribute(dn_hgemm<0>, cudaFuncAttributeMaxDynamicSharedMemorySize, SMEM_SZ);
    cudaFuncSetAttribute(dn_hgemm<1>, cudaFuncAttributeMaxDynamicSharedMemorySize, SMEM_SZ);

    cudaStream_t s1;
    cudaStreamCreateWithFlags(&s1, cudaStreamNonBlocking);
    cudaEvent_t evFork, evX, evRt, evJoin;
    cudaEventCreateWithFlags(&evFork, cudaEventDisableTiming);
    cudaEventCreateWithFlags(&evX,    cudaEventDisableTiming);
    cudaEventCreateWithFlags(&evRt,   cudaEventDisableTiming);
    cudaEventCreateWithFlags(&evJoin, cudaEventDisableTiming);

    cudaEventRecord(evFork, 0);
    cudaStreamWaitEvent(s1, evFork, 0);

    // ---- s1: zero out, router; then shared chain (after x is converted) ----
    cudaMemsetAsync(out, 0, (size_t)TT * HH * sizeof(float), s1);
    zero_cnt_kernel<<<1, 32, 0, s1>>>();
    router_kernel<<<TT / 8, 256, 0, s1>>>(x, wr, bias);
    cudaEventRecord(evRt, s1);

    // ---- s0: convert x to fp16 (the only convert left) ----
    cvt_kernel<<<(N_X / 8 + 255) / 256, 256>>>(
        (const float4*)x, (uint4*)p_xh, N_X / 8);
    cudaEventRecord(evX, 0);

    // ---- s1: shared experts (fp32 weights direct) ----
    cudaStreamWaitEvent(s1, evX, 0);
    gu_hgemm<<<dim3(MSHD / 64, TT / 128, 1), 256, SMEM_SZ, s1>>>(
        (const __half*)p_xh, shg, shu, (__half*)p_shact,
        nullptr, nullptr, HH, MSHD, 1, TT);
    dn_hgemm<1><<<dim3(HH / 128, TT / 128, 1), 256, SMEM_SZ, s1>>>(
        (const __half*)p_shact, shd, out,
        nullptr, nullptr, nullptr, MSHD, HH, TT, 1);
    cudaEventRecord(evJoin, s1);

    // ---- s0: routed experts (fp32 weights direct) ----
    cudaStreamWaitEvent(0, evRt, 0);   // router lists + memset (transitively)
    gu_hgemm<<<dim3(MI / 64, TT / 128, EE), 256, SMEM_SZ>>>(
        (const __half*)p_xh, gate_w, up_w, (__half*)p_act,
        (const int*)p_list, (const int*)p_cnt, HH, MI, KTOP, 0);
    dn_hgemm<1><<<dim3(HH / 128, TT / 128, EE), 256, SMEM_SZ>>>(
        (const __half*)p_act, down_w, out,
        (const int*)p_list, (const int*)p_cnt, (const float*)p_w,
        MI, HH, 0, KTOP);

    // join s1 into capture
    cudaStreamWaitEvent(0, evJoin, 0);
}